// round 2
// baseline (speedup 1.0000x reference)
#include <cuda_runtime.h>
#include <cuda_bf16.h>

// relu(sum(relu(x))) over N = 2^25 fp32. HBM-bound streaming reduction.
// Single fused kernel: grid-stride partials + last-block-done final reduce.
// Deterministic: partial order fixed; atomicInc only elects the finishing
// block, never touches float data. Counter self-resets -> graph-replayable.

#define NBLOCKS 1024
#define NTHREADS 256

__device__ float g_partials[NBLOCKS];
__device__ unsigned int g_count = 0;

__device__ __forceinline__ float block_reduce(float acc, float* warp_sums)
{
    #pragma unroll
    for (int off = 16; off > 0; off >>= 1)
        acc += __shfl_xor_sync(0xFFFFFFFFu, acc, off);

    int lane = threadIdx.x & 31;
    int wid = threadIdx.x >> 5;
    if (lane == 0) warp_sums[wid] = acc;
    __syncthreads();

    float s = 0.0f;
    if (wid == 0) {
        s = (lane < NTHREADS / 32) ? warp_sums[lane] : 0.0f;
        #pragma unroll
        for (int off = 16; off > 0; off >>= 1)
            s += __shfl_xor_sync(0xFFFFFFFFu, s, off);
    }
    return s;  // valid in warp 0 lane 0
}

__global__ __launch_bounds__(NTHREADS) void kan_fused_kernel(
    const float* __restrict__ x, int n_vec4, float* __restrict__ out)
{
    const float4* __restrict__ xv = reinterpret_cast<const float4*>(x);
    int tid = blockIdx.x * blockDim.x + threadIdx.x;
    int stride = gridDim.x * blockDim.x;

    float acc = 0.0f;
    // Unrolled x2 grid-stride: two independent float4 loads in flight per iter.
    int i = tid;
    for (; i + stride < n_vec4; i += 2 * stride) {
        float4 a = xv[i];
        float4 b = xv[i + stride];
        acc += fmaxf(a.x, 0.0f) + fmaxf(a.y, 0.0f)
             + fmaxf(a.z, 0.0f) + fmaxf(a.w, 0.0f);
        acc += fmaxf(b.x, 0.0f) + fmaxf(b.y, 0.0f)
             + fmaxf(b.z, 0.0f) + fmaxf(b.w, 0.0f);
    }
    if (i < n_vec4) {
        float4 a = xv[i];
        acc += fmaxf(a.x, 0.0f) + fmaxf(a.y, 0.0f)
             + fmaxf(a.z, 0.0f) + fmaxf(a.w, 0.0f);
    }

    __shared__ float warp_sums[NTHREADS / 32];
    float bsum = block_reduce(acc, warp_sums);

    // Publish partial, then elect the last block to finish.
    __shared__ bool is_last;
    if (threadIdx.x == 0) {
        g_partials[blockIdx.x] = bsum;
        __threadfence();
        unsigned int prev = atomicAdd(&g_count, 1u);
        is_last = (prev == (unsigned int)(gridDim.x - 1));
    }
    __syncthreads();

    if (is_last) {
        // 256 threads reduce NBLOCKS=1024 partials: 4 each, fixed order.
        float facc = 0.0f;
        #pragma unroll
        for (int k = 0; k < NBLOCKS / NTHREADS; k++)
            facc += g_partials[threadIdx.x + k * NTHREADS];

        __syncthreads();  // reuse warp_sums safely
        float total = block_reduce(facc, warp_sums);

        if (threadIdx.x == 0) {
            out[0] = fmaxf(total, 0.0f);  // outer relu
            g_count = 0;                  // reset for next graph replay
        }
    }
}

extern "C" void kernel_launch(void* const* d_in, const int* in_sizes, int n_in,
                              void* d_out, int out_size)
{
    const float* x = (const float*)d_in[0];
    float* out = (float*)d_out;
    int n = in_sizes[0];
    int n_vec4 = n / 4;  // N = 2^25, divisible by 4

    kan_fused_kernel<<<NBLOCKS, NTHREADS>>>(x, n_vec4, out);
}